// round 14
// baseline (speedup 1.0000x reference)
#include <cuda_runtime.h>
#include <cuda_bf16.h>
#include <cstdint>

// ---------------- problem constants ----------------
#define B     16
#define CIN   256
#define COUT  256
#define HW    4096
#define STY   512
#define KTOT  2304          // 9 taps * 256 ci; k = tap*256 + ci
#define NSTG  72            // K stages of 32

// ---------------- scratch ----------------
__device__ float g_s[B * CIN];
__device__ __align__(16) __nv_bfloat16 g_wbh[(size_t)B * COUT * KTOT]; // [b][co][k]
__device__ __align__(16) __nv_bfloat16 g_wbl[(size_t)B * COUT * KTOT];
__device__ __align__(16) __nv_bfloat16 g_xh[(size_t)B * HW * CIN];     // [b][pix][ci]
__device__ __align__(16) __nv_bfloat16 g_xl[(size_t)B * HW * CIN];
__device__ __align__(64) unsigned char g_zero64[64];                    // zero-init

// ---------------- helpers ----------------
__device__ __forceinline__ uint32_t smem_u32(const void* p) {
    uint32_t a;
    asm("{ .reg .u64 t; cvta.to.shared.u64 t, %1; cvt.u32.u64 %0, t; }" : "=r"(a) : "l"(p));
    return a;
}
__device__ __forceinline__ void ldsm_x4(uint32_t* r, uint32_t addr) {
    asm volatile("ldmatrix.sync.aligned.m8n8.x4.shared.b16 {%0,%1,%2,%3}, [%4];"
                 : "=r"(r[0]), "=r"(r[1]), "=r"(r[2]), "=r"(r[3]) : "r"(addr));
}
__device__ __forceinline__ void mma16816(float* c, const uint32_t* a,
                                         uint32_t b0, uint32_t b1) {
    asm volatile("mma.sync.aligned.m16n8k16.row.col.f32.bf16.bf16.f32 "
                 "{%0,%1,%2,%3}, {%4,%5,%6,%7}, {%8,%9}, {%0,%1,%2,%3};"
                 : "+f"(c[0]), "+f"(c[1]), "+f"(c[2]), "+f"(c[3])
                 : "r"(a[0]), "r"(a[1]), "r"(a[2]), "r"(a[3]), "r"(b0), "r"(b1));
}
__device__ __forceinline__ void cpa16(uint32_t dst, const void* src) {
    asm volatile("cp.async.ca.shared.global [%0], [%1], 16;" :: "r"(dst), "l"(src));
}
#define CPA_COMMIT() asm volatile("cp.async.commit_group;" ::: "memory")
#define CPA_WAIT0()  asm volatile("cp.async.wait_group 0;" ::: "memory")

// ---------------- smem layout: 80B-padded rows (64B data + pad) ----------------
// per buffer: AH 64 rows, AL 64, BH 128, BL 128 -> 384 rows * 80B = 30720B
#define ROWB    80
#define A_HI_O  0
#define A_LO_O  5120
#define B_HI_O  10240
#define B_LO_O  20480
#define BUFB    30720
#define SMEM_TOTAL (2 * BUFB)   // 61440 per CTA -> 2 CTAs/SM

// ---------------------------------------------------------------------------
__global__ void style_kernel(const float* __restrict__ w_style,
                             const float* __restrict__ aff_w,
                             const float* __restrict__ aff_b) {
    int warp = blockIdx.x * (blockDim.x >> 5) + (threadIdx.x >> 5);
    int lane = threadIdx.x & 31;
    if (warp >= B * CIN) return;
    int b  = warp / CIN;
    int ci = warp % CIN;
    const float4* ws = reinterpret_cast<const float4*>(w_style + (size_t)b * STY);
    const float4* aw = reinterpret_cast<const float4*>(aff_w  + (size_t)ci * STY);
    float sum = 0.f;
    #pragma unroll
    for (int j = lane; j < STY / 4; j += 32) {
        float4 a = ws[j], c = aw[j];
        sum += a.x * c.x + a.y * c.y + a.z * c.z + a.w * c.w;
    }
    #pragma unroll
    for (int o = 16; o; o >>= 1) sum += __shfl_xor_sync(0xffffffffu, sum, o);
    if (lane == 0) g_s[b * CIN + ci] = sum + aff_b[ci] + 1.0f;
}

// ---------------------------------------------------------------------------
__global__ void modulate_kernel(const float* __restrict__ Wf) {
    int co = blockIdx.x;
    int b  = blockIdx.y;
    int ci = threadIdx.x;

    float s = g_s[b * CIN + ci];
    const float* wp = Wf + ((size_t)co * CIN + ci) * 9;
    float m[9];
    float ss = 0.f;
    #pragma unroll
    for (int t = 0; t < 9; t++) { m[t] = wp[t] * s; ss += m[t] * m[t]; }

    __shared__ float red[256];
    red[ci] = ss;
    __syncthreads();
    #pragma unroll
    for (int st = 128; st > 0; st >>= 1) {
        if (ci < st) red[ci] += red[ci + st];
        __syncthreads();
    }
    float d = rsqrtf(red[0] + 1e-8f);

    size_t base = ((size_t)b * COUT + co) * KTOT;
    #pragma unroll
    for (int t = 0; t < 9; t++) {
        float w = m[t] * d;
        __nv_bfloat16 hi = __float2bfloat16_rn(w);
        __nv_bfloat16 lo = __float2bfloat16_rn(w - __bfloat162float(hi));
        g_wbh[base + t * 256 + ci] = hi;
        g_wbl[base + t * 256 + ci] = lo;
    }
}

// ---------------------------------------------------------------------------
__global__ void split_kernel(const float* __restrict__ x) {
    __shared__ float t[32][33];
    int b  = blockIdx.z;
    int cb = blockIdx.y * 32;
    int pb = blockIdx.x * 32;
    int tx = threadIdx.x, ty = threadIdx.y;

    const float* xp = x + ((size_t)b * CIN + cb) * HW + pb;
    #pragma unroll
    for (int i = ty; i < 32; i += 8)
        t[i][tx] = xp[(size_t)i * HW + tx];
    __syncthreads();
    #pragma unroll
    for (int i = ty; i < 32; i += 8) {
        float v = t[tx][i];
        __nv_bfloat16 h = __float2bfloat16_rn(v);
        size_t o = ((size_t)b * HW + pb + i) * CIN + cb + tx;
        g_xh[o] = h;
        g_xl[o] = __float2bfloat16_rn(v - __bfloat162float(h));
    }
}

// ---------------------------------------------------------------------------
// conv implicit GEMM. CTA: M=64 px (one image row), N=128 co, 256 thr =
// 8 warps (2M x 4N of 32x32 tiles). K staged 32, double buffer.
// B staged via cp.async, A via LDG->reg->STS (halo). One sync per stage.
// 2 CTAs/SM.
// ---------------------------------------------------------------------------
__global__ void __launch_bounds__(256, 2)
conv_kernel(float* __restrict__ out) {
    extern __shared__ __align__(16) char smem[];
    const uint32_t sbase = smem_u32(smem);

    const int tid   = threadIdx.x;
    const int wid   = tid >> 5;
    const int lane  = tid & 31;
    const int y0    = blockIdx.x;          // image row 0..63
    const int coT   = blockIdx.y;          // 0..1
    const int b     = blockIdx.z;
    const int coBase = coT * 128;

    const int wm = (wid & 1) * 32;         // warp M origin (0/32)
    const int wn = (wid >> 1) * 32;        // warp N origin (0..96)

    const int lr = lane & 15;
    const int kb = ((lane >> 4) & 1) * 16;

    // A staging: threads 0..127, one 64B row each
    const bool doA  = tid < 128;
    const int  aprec = (tid >> 6) & 1;     // 0=hi 1=lo
    const int  arow  = tid & 63;           // pixel x within the row
    // B staging: all threads, one 64B row each
    const int  bprec = tid >> 7;
    const int  brow  = tid & 127;          // local co

    const __nv_bfloat16* xsrc = (aprec ? g_xl : g_xh) + (size_t)b * HW * CIN;
    const __nv_bfloat16* wsrc = (bprec ? g_wbl : g_wbh)
                              + ((size_t)b * COUT + coBase + brow) * KTOT;

    float acc[2][4][4];
    #pragma unroll
    for (int i = 0; i < 2; i++)
        #pragma unroll
        for (int j = 0; j < 4; j++)
            #pragma unroll
            for (int q = 0; q < 4; q++) acc[i][j][q] = 0.f;

    uint4 v[4];
    auto ldgA = [&](int s) {
        if (!doA) return;
        int tap = s >> 3, ci0 = (s & 7) << 5;
        int y = y0 + tap / 3 - 1;
        int xx = arow + tap % 3 - 1;
        bool ok = (unsigned)y < 64u && (unsigned)xx < 64u;
        const uint4* sp = ok
            ? (const uint4*)(xsrc + ((size_t)(y * 64 + xx) * CIN + ci0))
            : (const uint4*)g_zero64;
        v[0] = sp[0]; v[1] = sp[1]; v[2] = sp[2]; v[3] = sp[3];
    };
    auto stsA = [&](int buf) {
        if (!doA) return;
        uint32_t dst = sbase + buf * BUFB + (aprec ? A_LO_O : A_HI_O) + arow * ROWB;
        *(uint4*)(smem + (dst - sbase))      = v[0];
        *(uint4*)(smem + (dst - sbase) + 16) = v[1];
        *(uint4*)(smem + (dst - sbase) + 32) = v[2];
        *(uint4*)(smem + (dst - sbase) + 48) = v[3];
    };
    auto cpaB = [&](int s, int buf) {
        const __nv_bfloat16* sw = wsrc + s * 32;
        uint32_t dst = sbase + buf * BUFB + (bprec ? B_LO_O : B_HI_O) + brow * ROWB;
        cpa16(dst,      sw);
        cpa16(dst + 16, sw + 8);
        cpa16(dst + 32, sw + 16);
        cpa16(dst + 48, sw + 24);
        CPA_COMMIT();
    };

    // prologue
    ldgA(0);
    cpaB(0, 0);
    stsA(0);
    ldgA(1);

    for (int s = 0; s < NSTG; s++) {
        const int buf = s & 1;
        CPA_WAIT0();            // B(s) landed
        __syncthreads();        // A(s) visible; previous readers of buf^1 done

        if (s + 1 < NSTG) cpaB(s + 1, buf ^ 1);

        const uint32_t bb = sbase + buf * BUFB;
        #pragma unroll
        for (int k16 = 0; k16 < 2; k16++) {
            const int kc = kb + k16 * 32;
            uint32_t ah[8], al[8], bh[8], bl[8];
            #pragma unroll
            for (int mt = 0; mt < 2; mt++)
                ldsm_x4(ah + mt * 4, bb + A_HI_O + (wm + mt * 16 + lr) * ROWB + kc);
            #pragma unroll
            for (int g = 0; g < 2; g++)
                ldsm_x4(bh + g * 4, bb + B_HI_O + (wn + g * 16 + lr) * ROWB + kc);
            // hh
            #pragma unroll
            for (int mt = 0; mt < 2; mt++)
                #pragma unroll
                for (int g = 0; g < 2; g++)
                    #pragma unroll
                    for (int j = 0; j < 2; j++)
                        mma16816(acc[mt][g * 2 + j], ah + mt * 4,
                                 bh[g * 4 + j], bh[g * 4 + j + 2]);
            // hl
            #pragma unroll
            for (int g = 0; g < 2; g++)
                ldsm_x4(bl + g * 4, bb + B_LO_O + (wn + g * 16 + lr) * ROWB + kc);
            #pragma unroll
            for (int mt = 0; mt < 2; mt++)
                #pragma unroll
                for (int g = 0; g < 2; g++)
                    #pragma unroll
                    for (int j = 0; j < 2; j++)
                        mma16816(acc[mt][g * 2 + j], ah + mt * 4,
                                 bl[g * 4 + j], bl[g * 4 + j + 2]);
            // lh
            #pragma unroll
            for (int mt = 0; mt < 2; mt++)
                ldsm_x4(al + mt * 4, bb + A_LO_O + (wm + mt * 16 + lr) * ROWB + kc);
            #pragma unroll
            for (int mt = 0; mt < 2; mt++)
                #pragma unroll
                for (int g = 0; g < 2; g++)
                    #pragma unroll
                    for (int j = 0; j < 2; j++)
                        mma16816(acc[mt][g * 2 + j], al + mt * 4,
                                 bh[g * 4 + j], bh[g * 4 + j + 2]);
        }

        if (s + 1 < NSTG) {
            stsA(buf ^ 1);              // store A(s+1)
            if (s + 2 < NSTG) ldgA(s + 2);
        }
    }

    // ---- epilogue: out[b][co][pix] ----
    float* ob = out + (size_t)b * COUT * HW;
    #pragma unroll
    for (int mt = 0; mt < 2; mt++) {
        int m = y0 * 64 + wm + mt * 16 + (lane >> 2);
        #pragma unroll
        for (int nt = 0; nt < 4; nt++) {
            int co = coBase + wn + nt * 8 + (lane & 3) * 2;
            const float* a = acc[mt][nt];
            float* p = ob + (size_t)co * HW + m;
            p[0]      = a[0];
            p[HW]     = a[1];
            p[8]      = a[2];
            p[HW + 8] = a[3];
        }
    }
}

// ---------------------------------------------------------------------------
extern "C" void kernel_launch(void* const* d_in, const int* in_sizes, int n_in,
                              void* d_out, int out_size) {
    const float* x       = (const float*)d_in[0];
    const float* w_style = (const float*)d_in[1];
    const float* Wf      = (const float*)d_in[2];
    const float* aff_w   = (const float*)d_in[3];
    const float* aff_b   = (const float*)d_in[4];
    float* out = (float*)d_out;

    style_kernel<<<(B * CIN + 7) / 8, 256>>>(w_style, aff_w, aff_b);
    modulate_kernel<<<dim3(COUT, B), 256>>>(Wf);
    split_kernel<<<dim3(HW / 32, CIN / 32, B), dim3(32, 8)>>>(x);

    cudaFuncSetAttribute(conv_kernel, cudaFuncAttributeMaxDynamicSharedMemorySize, SMEM_TOTAL);
    conv_kernel<<<dim3(64, 2, B), 256, SMEM_TOTAL>>>(out);
}

// round 15
// speedup vs baseline: 1.3519x; 1.3519x over previous
#include <cuda_runtime.h>
#include <cuda_bf16.h>
#include <cstdint>

// ---------------- problem constants ----------------
#define B     16
#define CIN   256
#define COUT  256
#define HW    4096
#define STY   512
#define KTOT  2304          // 9 taps * 256 ci; k = tap*256 + ci
#define KSTG  16
#define NSTG  144           // 2304 / 16

// ---------------- scratch ----------------
__device__ float g_s[B * CIN];
__device__ __align__(16) __nv_bfloat16 g_wbh[(size_t)B * COUT * KTOT]; // [b][co][k]
__device__ __align__(16) __nv_bfloat16 g_wbl[(size_t)B * COUT * KTOT];
__device__ __align__(16) __nv_bfloat16 g_xh[(size_t)B * HW * CIN];     // [b][pix][ci]
__device__ __align__(16) __nv_bfloat16 g_xl[(size_t)B * HW * CIN];
__device__ __align__(64) unsigned char g_zero64[64];                    // zero-init

// ---------------- helpers ----------------
__device__ __forceinline__ uint32_t smem_u32(const void* p) {
    uint32_t a;
    asm("{ .reg .u64 t; cvta.to.shared.u64 t, %1; cvt.u32.u64 %0, t; }" : "=r"(a) : "l"(p));
    return a;
}
__device__ __forceinline__ void ldsm_x4(uint32_t* r, uint32_t addr) {
    asm volatile("ldmatrix.sync.aligned.m8n8.x4.shared.b16 {%0,%1,%2,%3}, [%4];"
                 : "=r"(r[0]), "=r"(r[1]), "=r"(r[2]), "=r"(r[3]) : "r"(addr));
}
__device__ __forceinline__ void mma16816(float* c, const uint32_t* a,
                                         uint32_t b0, uint32_t b1) {
    asm volatile("mma.sync.aligned.m16n8k16.row.col.f32.bf16.bf16.f32 "
                 "{%0,%1,%2,%3}, {%4,%5,%6,%7}, {%8,%9}, {%0,%1,%2,%3};"
                 : "+f"(c[0]), "+f"(c[1]), "+f"(c[2]), "+f"(c[3])
                 : "r"(a[0]), "r"(a[1]), "r"(a[2]), "r"(a[3]), "r"(b0), "r"(b1));
}

// ---------------- smem: 48B-padded rows (32B data + 16B pad) ----------------
// per buffer: A_HI 128 rows, A_LO 128, B_HI 128, B_LO 128 -> 512*48 = 24576B
#define ROWB    48
#define A_HI_O  0
#define A_LO_O  6144
#define B_HI_O  12288
#define B_LO_O  18432
#define BUFB    24576
#define SMEM_TOTAL (3 * BUFB)   // 73728 -> 2 CTAs/SM

// ---------------------------------------------------------------------------
__global__ void style_kernel(const float* __restrict__ w_style,
                             const float* __restrict__ aff_w,
                             const float* __restrict__ aff_b) {
    int warp = blockIdx.x * (blockDim.x >> 5) + (threadIdx.x >> 5);
    int lane = threadIdx.x & 31;
    if (warp >= B * CIN) return;
    int b  = warp / CIN;
    int ci = warp % CIN;
    const float4* ws = reinterpret_cast<const float4*>(w_style + (size_t)b * STY);
    const float4* aw = reinterpret_cast<const float4*>(aff_w  + (size_t)ci * STY);
    float sum = 0.f;
    #pragma unroll
    for (int j = lane; j < STY / 4; j += 32) {
        float4 a = ws[j], c = aw[j];
        sum += a.x * c.x + a.y * c.y + a.z * c.z + a.w * c.w;
    }
    #pragma unroll
    for (int o = 16; o; o >>= 1) sum += __shfl_xor_sync(0xffffffffu, sum, o);
    if (lane == 0) g_s[b * CIN + ci] = sum + aff_b[ci] + 1.0f;
}

// ---------------------------------------------------------------------------
__global__ void modulate_kernel(const float* __restrict__ Wf) {
    int co = blockIdx.x;
    int b  = blockIdx.y;
    int ci = threadIdx.x;

    float s = g_s[b * CIN + ci];
    const float* wp = Wf + ((size_t)co * CIN + ci) * 9;
    float m[9];
    float ss = 0.f;
    #pragma unroll
    for (int t = 0; t < 9; t++) { m[t] = wp[t] * s; ss += m[t] * m[t]; }

    __shared__ float red[256];
    red[ci] = ss;
    __syncthreads();
    #pragma unroll
    for (int st = 128; st > 0; st >>= 1) {
        if (ci < st) red[ci] += red[ci + st];
        __syncthreads();
    }
    float d = rsqrtf(red[0] + 1e-8f);

    size_t base = ((size_t)b * COUT + co) * KTOT;
    #pragma unroll
    for (int t = 0; t < 9; t++) {
        float w = m[t] * d;
        __nv_bfloat16 hi = __float2bfloat16_rn(w);
        __nv_bfloat16 lo = __float2bfloat16_rn(w - __bfloat162float(hi));
        g_wbh[base + t * 256 + ci] = hi;
        g_wbl[base + t * 256 + ci] = lo;
    }
}

// ---------------------------------------------------------------------------
__global__ void split_kernel(const float* __restrict__ x) {
    __shared__ float t[32][33];
    int b  = blockIdx.z;
    int cb = blockIdx.y * 32;
    int pb = blockIdx.x * 32;
    int tx = threadIdx.x, ty = threadIdx.y;

    const float* xp = x + ((size_t)b * CIN + cb) * HW + pb;
    #pragma unroll
    for (int i = ty; i < 32; i += 8)
        t[i][tx] = xp[(size_t)i * HW + tx];
    __syncthreads();
    #pragma unroll
    for (int i = ty; i < 32; i += 8) {
        float v = t[tx][i];
        __nv_bfloat16 h = __float2bfloat16_rn(v);
        size_t o = ((size_t)b * HW + pb + i) * CIN + cb + tx;
        g_xh[o] = h;
        g_xl[o] = __float2bfloat16_rn(v - __bfloat162float(h));
    }
}

// ---------------------------------------------------------------------------
// conv implicit GEMM. CTA 128px x 128co, 256 thr = 8 warps (4M x 2N of
// 32x64 warp tiles). K staged 16, 3-buffer LDG->reg->STS pipeline,
// ONE __syncthreads per stage, 2 CTAs/SM.
// ---------------------------------------------------------------------------
__global__ void __launch_bounds__(256, 2)
conv_kernel(float* __restrict__ out) {
    extern __shared__ __align__(16) char smem[];
    const uint32_t sbase = smem_u32(smem);

    const int tid   = threadIdx.x;
    const int wid   = tid >> 5;
    const int lane  = tid & 31;
    const int strip = blockIdx.x;          // 0..31 (128-px strips)
    const int coT   = blockIdx.y;          // 0..1
    const int b     = blockIdx.z;
    const int coBase = coT * 128;

    const int wm = (wid & 3) * 32;         // warp M origin
    const int wn = (wid >> 2) * 64;        // warp N origin
    const int lr = lane & 15;
    const int kb = ((lane >> 4) & 1) * 16; // 16B column select

    // staging: each thread 1 A row (32B) + 1 B row (32B); prec by tid>>7
    const int prec = tid >> 7;             // 0=hi, 1=lo
    const int row  = tid & 127;            // pixel row / local co
    const int apy  = (strip * 128 + row) >> 6;
    const int apx  = (strip * 128 + row) & 63;

    const __nv_bfloat16* xsrc = (prec ? g_xl : g_xh) + (size_t)b * HW * CIN;
    const __nv_bfloat16* wsrc = (prec ? g_wbl : g_wbh)
                              + ((size_t)b * COUT + coBase + row) * KTOT;
    const uint32_t aoff = (prec ? A_LO_O : A_HI_O) + row * ROWB;
    const uint32_t boff = (prec ? B_LO_O : B_HI_O) + row * ROWB;

    float acc[2][8][4];
    #pragma unroll
    for (int i = 0; i < 2; i++)
        #pragma unroll
        for (int j = 0; j < 8; j++)
            #pragma unroll
            for (int q = 0; q < 4; q++) acc[i][j][q] = 0.f;

    uint4 va0, va1, vb0, vb1;
    auto ldg = [&](int s) {
        int tap = s >> 4, ci0 = (s & 15) << 4;
        int y = apy + tap / 3 - 1;
        int xx = apx + tap % 3 - 1;
        bool ok = (unsigned)y < 64u && (unsigned)xx < 64u;
        const uint4* ap = ok
            ? (const uint4*)(xsrc + ((size_t)(y * 64 + xx) * CIN + ci0))
            : (const uint4*)g_zero64;
        va0 = ap[0]; va1 = ap[1];
        const uint4* bp = (const uint4*)(wsrc + s * KSTG);
        vb0 = bp[0]; vb1 = bp[1];
    };
    auto sts = [&](int buf) {
        char* d = smem + buf * BUFB;
        *(uint4*)(d + aoff)      = va0;
        *(uint4*)(d + aoff + 16) = va1;
        *(uint4*)(d + boff)      = vb0;
        *(uint4*)(d + boff + 16) = vb1;
    };

    // prologue
    ldg(0); sts(0);
    ldg(1);
    __syncthreads();

    for (int s = 0; s < NSTG; s++) {
        const uint32_t bb = sbase + (s % 3) * BUFB;

        uint32_t ah[8], al[8];
        #pragma unroll
        for (int mt = 0; mt < 2; mt++) {
            ldsm_x4(ah + mt * 4, bb + A_HI_O + (wm + mt * 16 + lr) * ROWB + kb);
            ldsm_x4(al + mt * 4, bb + A_LO_O + (wm + mt * 16 + lr) * ROWB + kb);
        }
        #pragma unroll
        for (int g = 0; g < 4; g++) {
            uint32_t bh[4], bl[4];
            ldsm_x4(bh, bb + B_HI_O + (wn + g * 16 + lr) * ROWB + kb);
            ldsm_x4(bl, bb + B_LO_O + (wn + g * 16 + lr) * ROWB + kb);
            #pragma unroll
            for (int mt = 0; mt < 2; mt++)
                #pragma unroll
                for (int j = 0; j < 2; j++)
                    mma16816(acc[mt][g * 2 + j], ah + mt * 4, bh[j], bh[j + 2]);
            #pragma unroll
            for (int mt = 0; mt < 2; mt++)
                #pragma unroll
                for (int j = 0; j < 2; j++)
                    mma16816(acc[mt][g * 2 + j], ah + mt * 4, bl[j], bl[j + 2]);
            #pragma unroll
            for (int mt = 0; mt < 2; mt++)
                #pragma unroll
                for (int j = 0; j < 2; j++)
                    mma16816(acc[mt][g * 2 + j], al + mt * 4, bh[j], bh[j + 2]);
        }

        if (s + 1 < NSTG) sts((s + 1) % 3);   // buf (s+1)%3: readers (s-2) long done
        if (s + 2 < NSTG) ldg(s + 2);
        __syncthreads();
    }

    // ---- epilogue: out[b][co][pix] ----
    float* ob = out + (size_t)b * COUT * HW;
    #pragma unroll
    for (int mt = 0; mt < 2; mt++) {
        int m = strip * 128 + wm + mt * 16 + (lane >> 2);
        #pragma unroll
        for (int g = 0; g < 4; g++)
            #pragma unroll
            for (int j = 0; j < 2; j++) {
                int co = coBase + wn + g * 16 + j * 8 + (lane & 3) * 2;
                const float* a = acc[mt][g * 2 + j];
                float* p = ob + (size_t)co * HW + m;
                p[0]      = a[0];
                p[HW]     = a[1];
                p[8]      = a[2];
                p[HW + 8] = a[3];
            }
    }
}

// ---------------------------------------------------------------------------
extern "C" void kernel_launch(void* const* d_in, const int* in_sizes, int n_in,
                              void* d_out, int out_size) {
    const float* x       = (const float*)d_in[0];
    const float* w_style = (const float*)d_in[1];
    const float* Wf      = (const float*)d_in[2];
    const float* aff_w   = (const float*)d_in[3];
    const float* aff_b   = (const float*)d_in[4];
    float* out = (float*)d_out;

    style_kernel<<<(B * CIN + 7) / 8, 256>>>(w_style, aff_w, aff_b);
    modulate_kernel<<<dim3(COUT, B), 256>>>(Wf);
    split_kernel<<<dim3(HW / 32, CIN / 32, B), dim3(32, 8)>>>(x);

    cudaFuncSetAttribute(conv_kernel, cudaFuncAttributeMaxDynamicSharedMemorySize, SMEM_TOTAL);
    conv_kernel<<<dim3(32, 2, B), 256, SMEM_TOTAL>>>(out);
}

// round 16
// speedup vs baseline: 1.6960x; 1.2546x over previous
#include <cuda_runtime.h>
#include <cuda_bf16.h>
#include <cstdint>

// ---------------- problem constants ----------------
#define B     16
#define CIN   256
#define COUT  256
#define HW    4096
#define STY   512
#define KTOT  2304          // 9 taps * 256 ci; k = tap*256 + ci
#define KSTG  16
#define NSTG  144           // 2304 / 16

// ---------------- scratch ----------------
// weights: [b][stage s=tap*16+cib][co][16]   (stage-blocked, warp-coalesced)
// acts:    [b][cib][pix][16]                 (pixel-major within ci block)
__device__ float g_s[B * CIN];
__device__ __align__(16) __nv_bfloat16 g_wbh[(size_t)B * NSTG * COUT * 16];
__device__ __align__(16) __nv_bfloat16 g_wbl[(size_t)B * NSTG * COUT * 16];
__device__ __align__(16) __nv_bfloat16 g_xh[(size_t)B * 16 * HW * 16];
__device__ __align__(16) __nv_bfloat16 g_xl[(size_t)B * 16 * HW * 16];
__device__ __align__(64) unsigned char g_zero64[64];                    // zero-init

#define XB  ((size_t)16 * HW * 16)          // act elems per batch
#define WB  ((size_t)NSTG * COUT * 16)      // wgt elems per batch

// ---------------- helpers ----------------
__device__ __forceinline__ uint32_t smem_u32(const void* p) {
    uint32_t a;
    asm("{ .reg .u64 t; cvta.to.shared.u64 t, %1; cvt.u32.u64 %0, t; }" : "=r"(a) : "l"(p));
    return a;
}
__device__ __forceinline__ void ldsm_x4(uint32_t* r, uint32_t addr) {
    asm volatile("ldmatrix.sync.aligned.m8n8.x4.shared.b16 {%0,%1,%2,%3}, [%4];"
                 : "=r"(r[0]), "=r"(r[1]), "=r"(r[2]), "=r"(r[3]) : "r"(addr));
}
__device__ __forceinline__ void mma16816(float* c, const uint32_t* a,
                                         uint32_t b0, uint32_t b1) {
    asm volatile("mma.sync.aligned.m16n8k16.row.col.f32.bf16.bf16.f32 "
                 "{%0,%1,%2,%3}, {%4,%5,%6,%7}, {%8,%9}, {%0,%1,%2,%3};"
                 : "+f"(c[0]), "+f"(c[1]), "+f"(c[2]), "+f"(c[3])
                 : "r"(a[0]), "r"(a[1]), "r"(a[2]), "r"(a[3]), "r"(b0), "r"(b1));
}

// ---------------- smem: 48B-padded rows (32B data + 16B pad) ----------------
#define ROWB    48
#define A_HI_O  0
#define A_LO_O  6144
#define B_HI_O  12288
#define B_LO_O  18432
#define BUFB    24576
#define SMEM_TOTAL (3 * BUFB)   // 73728 -> 2 CTAs/SM

// ---------------------------------------------------------------------------
__global__ void style_kernel(const float* __restrict__ w_style,
                             const float* __restrict__ aff_w,
                             const float* __restrict__ aff_b) {
    int warp = blockIdx.x * (blockDim.x >> 5) + (threadIdx.x >> 5);
    int lane = threadIdx.x & 31;
    if (warp >= B * CIN) return;
    int b  = warp / CIN;
    int ci = warp % CIN;
    const float4* ws = reinterpret_cast<const float4*>(w_style + (size_t)b * STY);
    const float4* aw = reinterpret_cast<const float4*>(aff_w  + (size_t)ci * STY);
    float sum = 0.f;
    #pragma unroll
    for (int j = lane; j < STY / 4; j += 32) {
        float4 a = ws[j], c = aw[j];
        sum += a.x * c.x + a.y * c.y + a.z * c.z + a.w * c.w;
    }
    #pragma unroll
    for (int o = 16; o; o >>= 1) sum += __shfl_xor_sync(0xffffffffu, sum, o);
    if (lane == 0) g_s[b * CIN + ci] = sum + aff_b[ci] + 1.0f;
}

// ---------------------------------------------------------------------------
// modulate + demodulate -> g_wb[b][s][co][16], s = tap*16 + (ci>>4)
// ---------------------------------------------------------------------------
__global__ void modulate_kernel(const float* __restrict__ Wf) {
    int co = blockIdx.x;
    int b  = blockIdx.y;
    int ci = threadIdx.x;

    float s = g_s[b * CIN + ci];
    const float* wp = Wf + ((size_t)co * CIN + ci) * 9;
    float m[9];
    float ss = 0.f;
    #pragma unroll
    for (int t = 0; t < 9; t++) { m[t] = wp[t] * s; ss += m[t] * m[t]; }

    __shared__ float red[256];
    red[ci] = ss;
    __syncthreads();
    #pragma unroll
    for (int st = 128; st > 0; st >>= 1) {
        if (ci < st) red[ci] += red[ci + st];
        __syncthreads();
    }
    float d = rsqrtf(red[0] + 1e-8f);

    #pragma unroll
    for (int t = 0; t < 9; t++) {
        float w = m[t] * d;
        __nv_bfloat16 hi = __float2bfloat16_rn(w);
        __nv_bfloat16 lo = __float2bfloat16_rn(w - __bfloat162float(hi));
        int stg = t * 16 + (ci >> 4);
        size_t o = ((size_t)b * NSTG + stg) * (COUT * 16) + co * 16 + (ci & 15);
        g_wbh[o] = hi;
        g_wbl[o] = lo;
    }
}

// ---------------------------------------------------------------------------
// split/transpose x [b][ci][pix] fp32 -> [b][cib][pix][16] bf16 hi/lo
// ---------------------------------------------------------------------------
__global__ void split_kernel(const float* __restrict__ x) {
    __shared__ float t[32][33];
    int b  = blockIdx.z;
    int cb = blockIdx.y * 32;
    int pb = blockIdx.x * 32;
    int tx = threadIdx.x, ty = threadIdx.y;

    const float* xp = x + ((size_t)b * CIN + cb) * HW + pb;
    #pragma unroll
    for (int i = ty; i < 32; i += 8)
        t[i][tx] = xp[(size_t)i * HW + tx];
    __syncthreads();
    #pragma unroll
    for (int i = ty; i < 32; i += 8) {
        float v = t[tx][i];                      // ci = cb+tx, pix = pb+i
        __nv_bfloat16 h = __float2bfloat16_rn(v);
        int cib = (cb + tx) >> 4;
        size_t o = ((size_t)b * 16 + cib) * (HW * 16)
                 + (size_t)(pb + i) * 16 + (tx & 15);
        g_xh[o] = h;
        g_xl[o] = __float2bfloat16_rn(v - __bfloat162float(h));
    }
}

// ---------------------------------------------------------------------------
// conv implicit GEMM. CTA 128px x 128co, 256 thr = 8 warps (4M x 2N of
// 32x64 warp tiles). K staged 16, 3-buffer LDG->reg->STS pipeline,
// ONE __syncthreads per stage, 2 CTAs/SM. Coalesced stage-blocked LDG.
// ---------------------------------------------------------------------------
__global__ void __launch_bounds__(256, 2)
conv_kernel(float* __restrict__ out) {
    extern __shared__ __align__(16) char smem[];
    const uint32_t sbase = smem_u32(smem);

    const int tid   = threadIdx.x;
    const int wid   = tid >> 5;
    const int lane  = tid & 31;
    const int strip = blockIdx.x;          // 0..31 (128-px strips)
    const int coT   = blockIdx.y;          // 0..1
    const int b     = blockIdx.z;
    const int coBase = coT * 128;

    const int wm = (wid & 3) * 32;         // warp M origin
    const int wn = (wid >> 2) * 64;        // warp N origin
    const int lr = lane & 15;
    const int kb = ((lane >> 4) & 1) * 16; // 16B column select

    // staging: each thread 1 A row (32B) + 1 B row (32B); prec by tid>>7
    const int prec = tid >> 7;             // 0=hi, 1=lo
    const int row  = tid & 127;            // pixel row / local co
    const int apy  = (strip * 128 + row) >> 6;
    const int apx  = (strip * 128 + row) & 63;

    const __nv_bfloat16* xsrc = (prec ? g_xl : g_xh) + (size_t)b * XB;
    const __nv_bfloat16* wsrc = (prec ? g_wbl : g_wbh) + (size_t)b * WB
                              + (size_t)(coBase + row) * 16;
    const uint32_t aoff = (prec ? A_LO_O : A_HI_O) + row * ROWB;
    const uint32_t boff = (prec ? B_LO_O : B_HI_O) + row * ROWB;

    float acc[2][8][4];
    #pragma unroll
    for (int i = 0; i < 2; i++)
        #pragma unroll
        for (int j = 0; j < 8; j++)
            #pragma unroll
            for (int q = 0; q < 4; q++) acc[i][j][q] = 0.f;

    uint4 va0, va1, vb0, vb1;
    auto ldg = [&](int s) {
        int tap = s >> 4, cib = s & 15;
        int y = apy + tap / 3 - 1;
        int xx = apx + tap % 3 - 1;
        bool ok = (unsigned)y < 64u && (unsigned)xx < 64u;
        const uint4* ap = ok
            ? (const uint4*)(xsrc + ((size_t)cib * HW + (y * 64 + xx)) * 16)
            : (const uint4*)g_zero64;
        va0 = ap[0]; va1 = ap[1];
        const uint4* bp = (const uint4*)(wsrc + (size_t)s * (COUT * 16));
        vb0 = bp[0]; vb1 = bp[1];
    };
    auto sts = [&](int buf) {
        char* d = smem + buf * BUFB;
        *(uint4*)(d + aoff)      = va0;
        *(uint4*)(d + aoff + 16) = va1;
        *(uint4*)(d + boff)      = vb0;
        *(uint4*)(d + boff + 16) = vb1;
    };

    // prologue
    ldg(0); sts(0);
    ldg(1);
    __syncthreads();

    for (int s = 0; s < NSTG; s++) {
        const uint32_t bb = sbase + (s % 3) * BUFB;

        uint32_t ah[8], al[8];
        #pragma unroll
        for (int mt = 0; mt < 2; mt++) {
            ldsm_x4(ah + mt * 4, bb + A_HI_O + (wm + mt * 16 + lr) * ROWB + kb);
            ldsm_x4(al + mt * 4, bb + A_LO_O + (wm + mt * 16 + lr) * ROWB + kb);
        }
        #pragma unroll
        for (int g = 0; g < 4; g++) {
            uint32_t bh[4], bl[4];
            ldsm_x4(bh, bb + B_HI_O + (wn + g * 16 + lr) * ROWB + kb);
            ldsm_x4(bl, bb + B_LO_O + (wn + g * 16 + lr) * ROWB + kb);
            #pragma unroll
            for (int mt = 0; mt < 2; mt++)
                #pragma unroll
                for (int j = 0; j < 2; j++)
                    mma16816(acc[mt][g * 2 + j], ah + mt * 4, bh[j], bh[j + 2]);
            #pragma unroll
            for (int mt = 0; mt < 2; mt++)
                #pragma unroll
                for (int j = 0; j < 2; j++)
                    mma16816(acc[mt][g * 2 + j], ah + mt * 4, bl[j], bl[j + 2]);
            #pragma unroll
            for (int mt = 0; mt < 2; mt++)
                #pragma unroll
                for (int j = 0; j < 2; j++)
                    mma16816(acc[mt][g * 2 + j], al + mt * 4, bh[j], bh[j + 2]);
        }

        if (s + 1 < NSTG) sts((s + 1) % 3);   // buf (s+1)%3: readers (s-2) long done
        if (s + 2 < NSTG) ldg(s + 2);
        __syncthreads();
    }

    // ---- epilogue: out[b][co][pix] ----
    float* ob = out + (size_t)b * COUT * HW;
    #pragma unroll
    for (int mt = 0; mt < 2; mt++) {
        int m = strip * 128 + wm + mt * 16 + (lane >> 2);
        #pragma unroll
        for (int g = 0; g < 4; g++)
            #pragma unroll
            for (int j = 0; j < 2; j++) {
                int co = coBase + wn + g * 16 + j * 8 + (lane & 3) * 2;
                const float* a = acc[mt][g * 2 + j];
                float* p = ob + (size_t)co * HW + m;
                p[0]      = a[0];
                p[HW]     = a[1];
                p[8]      = a[2];
                p[HW + 8] = a[3];
            }
    }
}

// ---------------------------------------------------------------------------
extern "C" void kernel_launch(void* const* d_in, const int* in_sizes, int n_in,
                              void* d_out, int out_size) {
    const float* x       = (const float*)d_in[0];
    const float* w_style = (const float*)d_in[1];
    const float* Wf      = (const float*)d_in[2];
    const float* aff_w   = (const float*)d_in[3];
    const float* aff_b   = (const float*)d_in[4];
    float* out = (float*)d_out;

    style_kernel<<<(B * CIN + 7) / 8, 256>>>(w_style, aff_w, aff_b);
    modulate_kernel<<<dim3(COUT, B), 256>>>(Wf);
    split_kernel<<<dim3(HW / 32, CIN / 32, B), dim3(32, 8)>>>(x);

    cudaFuncSetAttribute(conv_kernel, cudaFuncAttributeMaxDynamicSharedMemorySize, SMEM_TOTAL);
    conv_kernel<<<dim3(32, 2, B), 256, SMEM_TOTAL>>>(out);
}